// round 1
// baseline (speedup 1.0000x reference)
#include <cuda_runtime.h>
#include <math.h>

// Problem constants
#define BB 4
#define SS 2048
#define FF 1024
#define DKK 1024

// GEMM tiling
#define BM 128
#define BN 128
#define BK 16
#define PAD 4

// Scratch (device globals — no allocations allowed)
__device__ float g_q[BB * SS * DKK];
__device__ float g_k[BB * SS * DKK];
__device__ float g_v[BB * SS * DKK];
__device__ float g_ctx[BB * SS * DKK];
__device__ float g_s[BB * SS * SS];
__device__ float g_rcpd[BB * SS];

// ---------------------------------------------------------------------------
// NT GEMM: C[m][n] = alpha * sum_k A[m][k] * B[n][k] + bias[n]
// A: (M,K) row-major, B: (N,K) row-major. Batched via blockIdx.z strides.
// ---------------------------------------------------------------------------
__global__ __launch_bounds__(256) void gemm_nt(
    const float* __restrict__ A, const float* __restrict__ B,
    float* __restrict__ C, const float* __restrict__ bias,
    int M, int N, int K, int lda, int ldb, int ldc,
    long sA, long sB, long sC, float alpha)
{
    __shared__ float As[BK][BM + PAD];
    __shared__ float Bs[BK][BN + PAD];

    int bz = blockIdx.z;
    A += (long)bz * sA;
    B += (long)bz * sB;
    C += (long)bz * sC;

    int bm = blockIdx.y * BM;
    int bn = blockIdx.x * BN;
    int tid = threadIdx.x;
    int warp = tid >> 5, lane = tid & 31;
    // warp tile: 32 (m) x 64 (n); 4x2 warp grid
    int m0 = (warp >> 1) * 32 + (lane >> 3) * 8;
    int n0 = (warp & 1) * 64 + (lane & 7) * 8;

    float acc[8][8];
#pragma unroll
    for (int i = 0; i < 8; i++)
#pragma unroll
        for (int j = 0; j < 8; j++) acc[i][j] = 0.0f;

    for (int k0 = 0; k0 < K; k0 += BK) {
        // Load A tile (BM x BK) and B tile (BN x BK), store k-major (transposed)
#pragma unroll
        for (int it = 0; it < 2; it++) {
            int id = tid + it * 256;        // 0..511
            int row = id >> 2;              // 0..127
            int c4 = (id & 3) << 2;         // 0,4,8,12
            float4 va = *(const float4*)(A + (long)(bm + row) * lda + k0 + c4);
            As[c4 + 0][row] = va.x;
            As[c4 + 1][row] = va.y;
            As[c4 + 2][row] = va.z;
            As[c4 + 3][row] = va.w;
            float4 vb = *(const float4*)(B + (long)(bn + row) * ldb + k0 + c4);
            Bs[c4 + 0][row] = vb.x;
            Bs[c4 + 1][row] = vb.y;
            Bs[c4 + 2][row] = vb.z;
            Bs[c4 + 3][row] = vb.w;
        }
        __syncthreads();

#pragma unroll
        for (int kk = 0; kk < BK; kk++) {
            float a[8], b[8];
            *(float4*)(&a[0]) = *(const float4*)(&As[kk][m0]);
            *(float4*)(&a[4]) = *(const float4*)(&As[kk][m0 + 4]);
            *(float4*)(&b[0]) = *(const float4*)(&Bs[kk][n0]);
            *(float4*)(&b[4]) = *(const float4*)(&Bs[kk][n0 + 4]);
#pragma unroll
            for (int i = 0; i < 8; i++)
#pragma unroll
                for (int j = 0; j < 8; j++) acc[i][j] += a[i] * b[j];
        }
        __syncthreads();
    }

    float bv[8];
#pragma unroll
    for (int j = 0; j < 8; j++) bv[j] = bias ? bias[bn + n0 + j] : 0.0f;

#pragma unroll
    for (int i = 0; i < 8; i++) {
        long r = (long)(bm + m0 + i) * ldc + bn + n0;
        float4 v0, v1;
        v0.x = alpha * acc[i][0] + bv[0];
        v0.y = alpha * acc[i][1] + bv[1];
        v0.z = alpha * acc[i][2] + bv[2];
        v0.w = alpha * acc[i][3] + bv[3];
        v1.x = alpha * acc[i][4] + bv[4];
        v1.y = alpha * acc[i][5] + bv[5];
        v1.z = alpha * acc[i][6] + bv[6];
        v1.w = alpha * acc[i][7] + bv[7];
        *(float4*)(C + r) = v0;
        *(float4*)(C + r + 4) = v1;
    }
}

// ---------------------------------------------------------------------------
// NN GEMM with per-k row scale on B:
// C[m][n] = sum_k A[m][k] * (B[k][n] * scale[k])
// Used for ctx = E @ (V * rcpD): folds the softmax denominator into V.
// ---------------------------------------------------------------------------
__global__ __launch_bounds__(256) void gemm_nn_scaled(
    const float* __restrict__ A, const float* __restrict__ B,
    const float* __restrict__ scale, float* __restrict__ C,
    int M, int N, int K, int lda, int ldb, int ldc,
    long sA, long sB, long sScale, long sC)
{
    __shared__ float As[BK][BM + PAD];
    __shared__ float Bs[BK][BN + PAD];

    int bz = blockIdx.z;
    A += (long)bz * sA;
    B += (long)bz * sB;
    C += (long)bz * sC;
    scale += (long)bz * sScale;

    int bm = blockIdx.y * BM;
    int bn = blockIdx.x * BN;
    int tid = threadIdx.x;
    int warp = tid >> 5, lane = tid & 31;
    int m0 = (warp >> 1) * 32 + (lane >> 3) * 8;
    int n0 = (warp & 1) * 64 + (lane & 7) * 8;

    float acc[8][8];
#pragma unroll
    for (int i = 0; i < 8; i++)
#pragma unroll
        for (int j = 0; j < 8; j++) acc[i][j] = 0.0f;

    for (int k0 = 0; k0 < K; k0 += BK) {
        // A tile (BM x BK) -> transposed store
#pragma unroll
        for (int it = 0; it < 2; it++) {
            int id = tid + it * 256;
            int row = id >> 2;
            int c4 = (id & 3) << 2;
            float4 va = *(const float4*)(A + (long)(bm + row) * lda + k0 + c4);
            As[c4 + 0][row] = va.x;
            As[c4 + 1][row] = va.y;
            As[c4 + 2][row] = va.z;
            As[c4 + 3][row] = va.w;
        }
        // B tile (BK x BN), natural k-major, scaled per k-row
#pragma unroll
        for (int it = 0; it < 2; it++) {
            int id = tid + it * 256;
            int row = id >> 5;              // 0..15 (k)
            int c4 = (id & 31) << 2;        // 0..124 (n)
            float r = __ldg(scale + k0 + row);
            float4 vb = *(const float4*)(B + (long)(k0 + row) * ldb + bn + c4);
            vb.x *= r; vb.y *= r; vb.z *= r; vb.w *= r;
            *(float4*)(&Bs[row][c4]) = vb;
        }
        __syncthreads();

#pragma unroll
        for (int kk = 0; kk < BK; kk++) {
            float a[8], b[8];
            *(float4*)(&a[0]) = *(const float4*)(&As[kk][m0]);
            *(float4*)(&a[4]) = *(const float4*)(&As[kk][m0 + 4]);
            *(float4*)(&b[0]) = *(const float4*)(&Bs[kk][n0]);
            *(float4*)(&b[4]) = *(const float4*)(&Bs[kk][n0 + 4]);
#pragma unroll
            for (int i = 0; i < 8; i++)
#pragma unroll
                for (int j = 0; j < 8; j++) acc[i][j] += a[i] * b[j];
        }
        __syncthreads();
    }

#pragma unroll
    for (int i = 0; i < 8; i++) {
        long r = (long)(bm + m0 + i) * ldc + bn + n0;
        float4 v0, v1;
        v0.x = acc[i][0]; v0.y = acc[i][1]; v0.z = acc[i][2]; v0.w = acc[i][3];
        v1.x = acc[i][4]; v1.y = acc[i][5]; v1.z = acc[i][6]; v1.w = acc[i][7];
        *(float4*)(C + r) = v0;
        *(float4*)(C + r + 4) = v1;
    }
}

// ---------------------------------------------------------------------------
// Column softmax stats: softmax over the QUERY axis (rows of S, per column k).
// Computes per-column max, overwrites S with exp(s - max), stores 1/sum.
// Block: 256 threads = 64 columns x 4 row-groups.
// ---------------------------------------------------------------------------
__global__ __launch_bounds__(256) void colsoftmax(
    float* __restrict__ Sm, float* __restrict__ rcpd, long bstride)
{
    __shared__ float red[4][64];
    int b = blockIdx.y;
    int cx = threadIdx.x & 63;
    int cy = threadIdx.x >> 6;
    int k = blockIdx.x * 64 + cx;
    float* p = Sm + (long)b * bstride + k;
    const int CH = SS / 4;
    int q0 = cy * CH;

    float m = -1e30f;
    for (int q = q0; q < q0 + CH; q++)
        m = fmaxf(m, p[(long)q * SS]);
    red[cy][cx] = m;
    __syncthreads();
    m = fmaxf(fmaxf(red[0][cx], red[1][cx]), fmaxf(red[2][cx], red[3][cx]));
    __syncthreads();

    float sum = 0.0f;
    for (int q = q0; q < q0 + CH; q++) {
        float e = __expf(p[(long)q * SS] - m);
        sum += e;
        p[(long)q * SS] = e;
    }
    red[cy][cx] = sum;
    __syncthreads();
    if (cy == 0) {
        float d = red[0][cx] + red[1][cx] + red[2][cx] + red[3][cx];
        rcpd[(long)b * SS + k] = 1.0f / d;
    }
}

// ---------------------------------------------------------------------------
extern "C" void kernel_launch(void* const* d_in, const int* in_sizes, int n_in,
                              void* d_out, int out_size)
{
    const float* x  = (const float*)d_in[0];
    const float* Wq = (const float*)d_in[1];
    const float* bq = (const float*)d_in[2];
    const float* Wk = (const float*)d_in[3];
    const float* bk = (const float*)d_in[4];
    const float* Wv = (const float*)d_in[5];
    const float* bv = (const float*)d_in[6];
    const float* Wo = (const float*)d_in[7];
    const float* bo = (const float*)d_in[8];

    float *q, *k, *v, *ctx, *s, *rcpd;
    cudaGetSymbolAddress((void**)&q,    g_q);
    cudaGetSymbolAddress((void**)&k,    g_k);
    cudaGetSymbolAddress((void**)&v,    g_v);
    cudaGetSymbolAddress((void**)&ctx,  g_ctx);
    cudaGetSymbolAddress((void**)&s,    g_s);
    cudaGetSymbolAddress((void**)&rcpd, g_rcpd);

    const int M = BB * SS;  // 8192
    dim3 blk(256);

    // 1) QKV projections: y = x @ W^T + b  (NT GEMM)
    dim3 g1(DKK / BN, M / BM, 1);
    gemm_nt<<<g1, blk>>>(x, Wq, q, bq, M, DKK, FF, FF, FF, DKK, 0, 0, 0, 1.0f);
    gemm_nt<<<g1, blk>>>(x, Wk, k, bk, M, DKK, FF, FF, FF, DKK, 0, 0, 0, 1.0f);
    gemm_nt<<<g1, blk>>>(x, Wv, v, bv, M, DKK, FF, FF, FF, DKK, 0, 0, 0, 1.0f);

    // 2) scores = (q @ k^T) / sqrt(DK)   (batched NT GEMM)
    dim3 g2(SS / BN, SS / BM, BB);
    gemm_nt<<<g2, blk>>>(q, k, s, nullptr, SS, SS, DKK, DKK, DKK, SS,
                         (long)SS * DKK, (long)SS * DKK, (long)SS * SS,
                         1.0f / 32.0f);

    // 3) column softmax stats (softmax over query axis): S <- exp(S - colmax),
    //    rcpd <- 1/colsum
    dim3 g3(SS / 64, BB);
    colsoftmax<<<g3, blk>>>(s, rcpd, (long)SS * SS);

    // 4) ctx = E @ (V * rcpd)   (batched NN GEMM with folded denominator)
    dim3 g4(DKK / BN, SS / BM, BB);
    gemm_nn_scaled<<<g4, blk>>>(s, v, rcpd, ctx, SS, DKK, SS, SS, DKK, DKK,
                                (long)SS * SS, (long)SS * DKK, SS,
                                (long)SS * DKK);

    // 5) out = ctx @ Wo^T + bo   (NT GEMM)
    dim3 g5(FF / BN, M / BM, 1);
    gemm_nt<<<g5, blk>>>(ctx, Wo, (float*)d_out, bo, M, FF, DKK, DKK, DKK, FF,
                         0, 0, 0, 1.0f);
}

// round 3
// speedup vs baseline: 2.0330x; 2.0330x over previous
#include <cuda_runtime.h>
#include <cuda_bf16.h>
#include <cstdint>

#define BB 4
#define SS 2048
#define FF 1024
#define DKK 1024

// ---------------- scratch (device globals; no allocs allowed) ----------------
__device__ __nv_bfloat16 g_xhi[BB*SS*FF],  g_xlo[BB*SS*FF];
__device__ __nv_bfloat16 g_Wqhi[DKK*FF],   g_Wqlo[DKK*FF];
__device__ __nv_bfloat16 g_Wkhi[DKK*FF],   g_Wklo[DKK*FF];
__device__ __nv_bfloat16 g_Wvhi[DKK*FF],   g_Wvlo[DKK*FF];
__device__ __nv_bfloat16 g_Wohi[FF*DKK],   g_Wolo[FF*DKK];
__device__ __nv_bfloat16 g_qhi[BB*SS*DKK], g_qlo[BB*SS*DKK];
__device__ __nv_bfloat16 g_khi[BB*SS*DKK], g_klo[BB*SS*DKK];
__device__ __nv_bfloat16 g_vhi[BB*SS*DKK], g_vlo[BB*SS*DKK];
__device__ __nv_bfloat16 g_vThi[BB*DKK*SS], g_vTlo[BB*DKK*SS];
__device__ float         g_s[(size_t)BB*SS*SS];
__device__ __nv_bfloat16 g_Ehi[(size_t)BB*SS*SS], g_Elo[(size_t)BB*SS*SS];
__device__ __nv_bfloat16 g_chi[BB*SS*DKK], g_clo[BB*SS*DKK];

// ---------------- PTX helpers (arch-portable: sm_80+ features only) ----------
__device__ __forceinline__ uint32_t smem_to_u32(const void* p) {
    uint32_t a;
    asm("{ .reg .u64 t; cvta.to.shared.u64 t, %1; cvt.u32.u64 %0, t; }" : "=r"(a) : "l"(p));
    return a;
}
__device__ __forceinline__ void cp16(uint32_t dst, const void* src) {
    asm volatile("cp.async.cg.shared.global [%0], [%1], 16;" :: "r"(dst), "l"(src));
}
#define CP_COMMIT() asm volatile("cp.async.commit_group;" ::: "memory")
template <int N> __device__ __forceinline__ void cp_wait() {
    asm volatile("cp.async.wait_group %0;" :: "n"(N) : "memory");
}
__device__ __forceinline__ void ldmx4(uint32_t* r, uint32_t addr) {
    asm volatile("ldmatrix.sync.aligned.m8n8.x4.shared.b16 {%0,%1,%2,%3}, [%4];"
        : "=r"(r[0]), "=r"(r[1]), "=r"(r[2]), "=r"(r[3]) : "r"(addr));
}
__device__ __forceinline__ void mma16816(float* c, const uint32_t* a, const uint32_t* b) {
    asm volatile(
        "mma.sync.aligned.m16n8k16.row.col.f32.bf16.bf16.f32 "
        "{%0,%1,%2,%3}, {%4,%5,%6,%7}, {%8,%9}, {%0,%1,%2,%3};"
        : "+f"(c[0]), "+f"(c[1]), "+f"(c[2]), "+f"(c[3])
        : "r"(a[0]), "r"(a[1]), "r"(a[2]), "r"(a[3]), "r"(b[0]), "r"(b[1]));
}

// smem geometry: 4 planes of 128 rows x 32 bf16, row stride 112 bytes
// (112*i mod 128 covers all eight 16B segments -> conflict-free ldmatrix)
#define STRB   112
#define PLANE  (128 * STRB)          // 14336 B
#define BUFSZ  (4 * PLANE)           // 57344 B
#define SMEM_TOTAL (2 * BUFSZ)       // 114688 B

// ---------------------------------------------------------------------------
// NT GEMM via mma.sync, bf16 hi/lo split (3 MMA terms):
//   C = alpha * (A . B^T) + bias,   A: M x K, B: N x K (both K-contiguous)
// Output fp32 (Cf) and/or bf16 hi/lo planes (Chi/Clo).
// ---------------------------------------------------------------------------
__global__ __launch_bounds__(256) void gemm_tc(
    const __nv_bfloat16* __restrict__ Ahi, const __nv_bfloat16* __restrict__ Alo,
    const __nv_bfloat16* __restrict__ Bhi, const __nv_bfloat16* __restrict__ Blo,
    float* __restrict__ Cf, __nv_bfloat16* __restrict__ Chi, __nv_bfloat16* __restrict__ Clo,
    const float* __restrict__ bias,
    int K, int lda, int ldb, int ldc,
    long long sA, long long sB, long long sC, float alpha)
{
    extern __shared__ char smem[];
    uint32_t sbase = smem_to_u32(smem);
    int tid = threadIdx.x;
    int lane = tid & 31;
    int warp = tid >> 5;
    int m0w = (warp >> 1) * 32;     // warp tile 32(m) x 64(n), 4x2 warps
    int n0w = (warp & 1) * 64;

    int bz = blockIdx.z;
    size_t bm = (size_t)blockIdx.y * 128;
    size_t bn = (size_t)blockIdx.x * 128;

    const __nv_bfloat16* A0 = Ahi + (size_t)bz * sA + bm * lda;
    const __nv_bfloat16* A1 = Alo + (size_t)bz * sA + bm * lda;
    const __nv_bfloat16* B0 = Bhi + (size_t)bz * sB + bn * ldb;
    const __nv_bfloat16* B1 = Blo + (size_t)bz * sB + bn * ldb;

    float acc[2][8][4];
#pragma unroll
    for (int i = 0; i < 2; i++)
#pragma unroll
        for (int j = 0; j < 8; j++)
#pragma unroll
            for (int t = 0; t < 4; t++) acc[i][j][t] = 0.0f;

    int nch = K >> 5;   // K/32 chunks

    auto prefetch = [&](int c) {
        int k0 = c << 5;
        uint32_t sb = sbase + (uint32_t)(c & 1) * BUFSZ;
#pragma unroll
        for (int it = 0; it < 2; it++) {
            int id = tid + it * 256;          // 0..511
            int row = id >> 2;                // 0..127
            int seg = id & 3;                 // 0..3 (16B segments of 64B row)
            uint32_t doff = (uint32_t)(row * STRB + seg * 16);
            size_t ea = (size_t)row * lda + k0 + seg * 8;
            size_t eb = (size_t)row * ldb + k0 + seg * 8;
            cp16(sb + 0 * PLANE + doff, A0 + ea);
            cp16(sb + 1 * PLANE + doff, A1 + ea);
            cp16(sb + 2 * PLANE + doff, B0 + eb);
            cp16(sb + 3 * PLANE + doff, B1 + eb);
        }
    };

    // per-lane ldmatrix address pieces
    int aRow = m0w + (lane & 15);
    uint32_t aColB = (uint32_t)((lane >> 4) * 16);
    int bRow = n0w + ((lane >> 4) << 3) + (lane & 7);
    uint32_t bColB = (uint32_t)(((lane >> 3) & 1) * 16);

    prefetch(0);
    CP_COMMIT();

    for (int c = 0; c < nch; c++) {
        if (c + 1 < nch) {
            prefetch(c + 1);
            CP_COMMIT();
            cp_wait<1>();
        } else {
            cp_wait<0>();
        }
        __syncthreads();

        uint32_t sb = sbase + (uint32_t)(c & 1) * BUFSZ;
#pragma unroll
        for (int ks = 0; ks < 2; ks++) {
            uint32_t kB = (uint32_t)(ks * 32);
            uint32_t a_hi[2][4], a_lo[2][4];
#pragma unroll
            for (int mf = 0; mf < 2; mf++) {
                uint32_t off = (uint32_t)((aRow + mf * 16) * STRB) + kB + aColB;
                ldmx4(a_hi[mf], sb + 0 * PLANE + off);
                ldmx4(a_lo[mf], sb + 1 * PLANE + off);
            }
            uint32_t b_hi[16], b_lo[16];
#pragma unroll
            for (int ng = 0; ng < 4; ng++) {
                uint32_t off = (uint32_t)((bRow + ng * 16) * STRB) + kB + bColB;
                ldmx4(&b_hi[ng * 4], sb + 2 * PLANE + off);
                ldmx4(&b_lo[ng * 4], sb + 3 * PLANE + off);
            }
#pragma unroll
            for (int mf = 0; mf < 2; mf++)
#pragma unroll
                for (int nf = 0; nf < 8; nf++) {
                    mma16816(acc[mf][nf], a_hi[mf], &b_hi[nf * 2]);
                    mma16816(acc[mf][nf], a_hi[mf], &b_lo[nf * 2]);
                    mma16816(acc[mf][nf], a_lo[mf], &b_hi[nf * 2]);
                }
        }
        __syncthreads();
    }

    // epilogue
    int gidr = lane >> 2;         // groupID
    int tidq = lane & 3;          // threadID in group
#pragma unroll
    for (int mf = 0; mf < 2; mf++) {
#pragma unroll
        for (int nf = 0; nf < 8; nf++) {
            size_t r0 = bm + m0w + mf * 16 + gidr;
            size_t r1 = r0 + 8;
            size_t col = bn + n0w + nf * 8 + tidq * 2;
            float b0 = bias ? bias[col] : 0.0f;
            float b1 = bias ? bias[col + 1] : 0.0f;
            float c00 = acc[mf][nf][0] * alpha + b0;
            float c01 = acc[mf][nf][1] * alpha + b1;
            float c10 = acc[mf][nf][2] * alpha + b0;
            float c11 = acc[mf][nf][3] * alpha + b1;
            if (Cf) {
                float* base = Cf + (size_t)bz * sC;
                *(float2*)(base + r0 * ldc + col) = make_float2(c00, c01);
                *(float2*)(base + r1 * ldc + col) = make_float2(c10, c11);
            }
            if (Chi) {
                __nv_bfloat16* bh = Chi + (size_t)bz * sC;
                __nv_bfloat16* bl = Clo + (size_t)bz * sC;
                __nv_bfloat162 h0 = __floats2bfloat162_rn(c00, c01);
                __nv_bfloat162 h1 = __floats2bfloat162_rn(c10, c11);
                __nv_bfloat162 l0 = __floats2bfloat162_rn(
                    c00 - __bfloat162float(__low2bfloat16(h0)),
                    c01 - __bfloat162float(__high2bfloat16(h0)));
                __nv_bfloat162 l1 = __floats2bfloat162_rn(
                    c10 - __bfloat162float(__low2bfloat16(h1)),
                    c11 - __bfloat162float(__high2bfloat16(h1)));
                *(__nv_bfloat162*)(bh + r0 * ldc + col) = h0;
                *(__nv_bfloat162*)(bh + r1 * ldc + col) = h1;
                *(__nv_bfloat162*)(bl + r0 * ldc + col) = l0;
                *(__nv_bfloat162*)(bl + r1 * ldc + col) = l1;
            }
        }
    }
}

// ---------------------------------------------------------------------------
// fp32 -> bf16 hi/lo split conversion
// ---------------------------------------------------------------------------
__global__ __launch_bounds__(256) void conv_split(
    const float* __restrict__ in, __nv_bfloat16* __restrict__ hi,
    __nv_bfloat16* __restrict__ lo, long long n4)
{
    long long i = (long long)blockIdx.x * blockDim.x + threadIdx.x;
    if (i >= n4) return;
    float4 v = ((const float4*)in)[i];
    __nv_bfloat162 h0 = __floats2bfloat162_rn(v.x, v.y);
    __nv_bfloat162 h1 = __floats2bfloat162_rn(v.z, v.w);
    float r0 = v.x - __bfloat162float(__low2bfloat16(h0));
    float r1 = v.y - __bfloat162float(__high2bfloat16(h0));
    float r2 = v.z - __bfloat162float(__low2bfloat16(h1));
    float r3 = v.w - __bfloat162float(__high2bfloat16(h1));
    ((__nv_bfloat162*)hi)[2 * i] = h0;
    ((__nv_bfloat162*)hi)[2 * i + 1] = h1;
    ((__nv_bfloat162*)lo)[2 * i] = __floats2bfloat162_rn(r0, r1);
    ((__nv_bfloat162*)lo)[2 * i + 1] = __floats2bfloat162_rn(r2, r3);
}

// ---------------------------------------------------------------------------
// Column softmax (over query axis) with folded 1/sum; writes E hi/lo bf16.
// ---------------------------------------------------------------------------
__global__ __launch_bounds__(256) void colsoftmax(
    const float* __restrict__ S, __nv_bfloat16* __restrict__ Ehi,
    __nv_bfloat16* __restrict__ Elo)
{
    __shared__ float red[4][64];
    int b = blockIdx.y;
    int cx = threadIdx.x & 63;
    int cy = threadIdx.x >> 6;
    size_t k = (size_t)blockIdx.x * 64 + cx;
    const float* p = S + (size_t)b * SS * SS + k;
    const int CH = SS / 4;
    int q0 = cy * CH;

    float m = -1e30f;
    for (int q = q0; q < q0 + CH; q++)
        m = fmaxf(m, p[(size_t)q * SS]);
    red[cy][cx] = m;
    __syncthreads();
    m = fmaxf(fmaxf(red[0][cx], red[1][cx]), fmaxf(red[2][cx], red[3][cx]));
    __syncthreads();

    float sum = 0.0f;
    for (int q = q0; q < q0 + CH; q++)
        sum += __expf(p[(size_t)q * SS] - m);
    red[cy][cx] = sum;
    __syncthreads();
    float rcp = 1.0f / (red[0][cx] + red[1][cx] + red[2][cx] + red[3][cx]);

    __nv_bfloat16* eh = Ehi + (size_t)b * SS * SS + k;
    __nv_bfloat16* el = Elo + (size_t)b * SS * SS + k;
    for (int q = q0; q < q0 + CH; q++) {
        float e = __expf(p[(size_t)q * SS] - m) * rcp;
        __nv_bfloat16 h = __float2bfloat16(e);
        eh[(size_t)q * SS] = h;
        el[(size_t)q * SS] = __float2bfloat16(e - __bfloat162float(h));
    }
}

// ---------------------------------------------------------------------------
// bf16 transpose (both planes), batched.
// ---------------------------------------------------------------------------
__global__ __launch_bounds__(256) void transpose2(
    const __nv_bfloat16* __restrict__ ihi, const __nv_bfloat16* __restrict__ ilo,
    __nv_bfloat16* __restrict__ ohi, __nv_bfloat16* __restrict__ olo,
    int rows, int cols)
{
    __shared__ __nv_bfloat16 t[32][33];
    int z = blockIdx.z;
    size_t ioff = (size_t)z * rows * cols;
    int c0 = blockIdx.x * 32, r0 = blockIdx.y * 32;
    int tx = threadIdx.x, ty = threadIdx.y;

    const __nv_bfloat16* src = ihi + ioff;
    __nv_bfloat16* dst = ohi + ioff;
#pragma unroll
    for (int j = 0; j < 32; j += 8)
        t[ty + j][tx] = src[(size_t)(r0 + ty + j) * cols + c0 + tx];
    __syncthreads();
#pragma unroll
    for (int j = 0; j < 32; j += 8)
        dst[(size_t)(c0 + ty + j) * rows + r0 + tx] = t[tx][ty + j];
    __syncthreads();

    src = ilo + ioff;
    dst = olo + ioff;
#pragma unroll
    for (int j = 0; j < 32; j += 8)
        t[ty + j][tx] = src[(size_t)(r0 + ty + j) * cols + c0 + tx];
    __syncthreads();
#pragma unroll
    for (int j = 0; j < 32; j += 8)
        dst[(size_t)(c0 + ty + j) * rows + r0 + tx] = t[tx][ty + j];
}

// ---------------------------------------------------------------------------
extern "C" void kernel_launch(void* const* d_in, const int* in_sizes, int n_in,
                              void* d_out, int out_size)
{
    const float* x  = (const float*)d_in[0];
    const float* Wq = (const float*)d_in[1];
    const float* bq = (const float*)d_in[2];
    const float* Wk = (const float*)d_in[3];
    const float* bk = (const float*)d_in[4];
    const float* Wv = (const float*)d_in[5];
    const float* bv = (const float*)d_in[6];
    const float* Wo = (const float*)d_in[7];
    const float* bo = (const float*)d_in[8];

    __nv_bfloat16 *xhi, *xlo, *Wqhi, *Wqlo, *Wkhi, *Wklo, *Wvhi, *Wvlo, *Wohi, *Wolo;
    __nv_bfloat16 *qhi, *qlo, *khi, *klo, *vhi, *vlo, *vThi, *vTlo, *Ehi, *Elo, *chi, *clo;
    float* s;
    cudaGetSymbolAddress((void**)&xhi, g_xhi);   cudaGetSymbolAddress((void**)&xlo, g_xlo);
    cudaGetSymbolAddress((void**)&Wqhi, g_Wqhi); cudaGetSymbolAddress((void**)&Wqlo, g_Wqlo);
    cudaGetSymbolAddress((void**)&Wkhi, g_Wkhi); cudaGetSymbolAddress((void**)&Wklo, g_Wklo);
    cudaGetSymbolAddress((void**)&Wvhi, g_Wvhi); cudaGetSymbolAddress((void**)&Wvlo, g_Wvlo);
    cudaGetSymbolAddress((void**)&Wohi, g_Wohi); cudaGetSymbolAddress((void**)&Wolo, g_Wolo);
    cudaGetSymbolAddress((void**)&qhi, g_qhi);   cudaGetSymbolAddress((void**)&qlo, g_qlo);
    cudaGetSymbolAddress((void**)&khi, g_khi);   cudaGetSymbolAddress((void**)&klo, g_klo);
    cudaGetSymbolAddress((void**)&vhi, g_vhi);   cudaGetSymbolAddress((void**)&vlo, g_vlo);
    cudaGetSymbolAddress((void**)&vThi, g_vThi); cudaGetSymbolAddress((void**)&vTlo, g_vTlo);
    cudaGetSymbolAddress((void**)&Ehi, g_Ehi);   cudaGetSymbolAddress((void**)&Elo, g_Elo);
    cudaGetSymbolAddress((void**)&chi, g_chi);   cudaGetSymbolAddress((void**)&clo, g_clo);
    cudaGetSymbolAddress((void**)&s, g_s);

    cudaFuncSetAttribute(gemm_tc, cudaFuncAttributeMaxDynamicSharedMemorySize, SMEM_TOTAL);

    const int M = BB * SS;  // 8192
    dim3 blk(256);

    // 0) conversions
    conv_split<<<(M * FF / 4 + 255) / 256, 256>>>(x, xhi, xlo, (long long)M * FF / 4);
    conv_split<<<(DKK * FF / 4 + 255) / 256, 256>>>(Wq, Wqhi, Wqlo, (long long)DKK * FF / 4);
    conv_split<<<(DKK * FF / 4 + 255) / 256, 256>>>(Wk, Wkhi, Wklo, (long long)DKK * FF / 4);
    conv_split<<<(DKK * FF / 4 + 255) / 256, 256>>>(Wv, Wvhi, Wvlo, (long long)DKK * FF / 4);
    conv_split<<<(FF * DKK / 4 + 255) / 256, 256>>>(Wo, Wohi, Wolo, (long long)FF * DKK / 4);

    // 1) QKV projections -> bf16 hi/lo (+bias)
    dim3 g1(DKK / 128, M / 128, 1);
    gemm_tc<<<g1, blk, SMEM_TOTAL>>>(xhi, xlo, Wqhi, Wqlo, nullptr, qhi, qlo, bq,
                                     FF, FF, FF, DKK, 0, 0, 0, 1.0f);
    gemm_tc<<<g1, blk, SMEM_TOTAL>>>(xhi, xlo, Wkhi, Wklo, nullptr, khi, klo, bk,
                                     FF, FF, FF, DKK, 0, 0, 0, 1.0f);
    gemm_tc<<<g1, blk, SMEM_TOTAL>>>(xhi, xlo, Wvhi, Wvlo, nullptr, vhi, vlo, bv,
                                     FF, FF, FF, DKK, 0, 0, 0, 1.0f);

    // 2) scores = (q k^T)/32 -> fp32 S (batched)
    dim3 g2(SS / 128, SS / 128, BB);
    gemm_tc<<<g2, blk, SMEM_TOTAL>>>(qhi, qlo, khi, klo, s, nullptr, nullptr, nullptr,
                                     DKK, DKK, DKK, SS,
                                     (long long)SS * DKK, (long long)SS * DKK,
                                     (long long)SS * SS, 1.0f / 32.0f);

    // 3) column softmax -> E hi/lo (1/sum folded)
    dim3 g3(SS / 64, BB);
    colsoftmax<<<g3, blk>>>(s, Ehi, Elo);

    // 4) transpose v -> vT (per batch)
    dim3 g4(DKK / 32, SS / 32, BB);
    transpose2<<<g4, dim3(32, 8)>>>(vhi, vlo, vThi, vTlo, SS, DKK);

    // 5) ctx = E @ V  (NT with B = vT) -> bf16 hi/lo
    dim3 g5(DKK / 128, SS / 128, BB);
    gemm_tc<<<g5, blk, SMEM_TOTAL>>>(Ehi, Elo, vThi, vTlo, nullptr, chi, clo, nullptr,
                                     SS, SS, SS, DKK,
                                     (long long)SS * SS, (long long)DKK * SS,
                                     (long long)SS * DKK, 1.0f);

    // 6) out = ctx @ Wo^T + bo -> fp32
    dim3 g6(FF / 128, M / 128, 1);
    gemm_tc<<<g6, blk, SMEM_TOTAL>>>(chi, clo, Wohi, Wolo, (float*)d_out, nullptr, nullptr, bo,
                                     DKK, DKK, DKK, FF, 0, 0, 0, 1.0f);
}

// round 4
// speedup vs baseline: 2.3701x; 1.1658x over previous
#include <cuda_runtime.h>
#include <cuda_bf16.h>
#include <cstdint>

#define BB 4
#define SS 2048
#define FF 1024
#define DKK 1024

// ---------------- scratch (device globals; no allocs allowed) ----------------
__device__ __nv_bfloat16 g_xhi[BB*SS*FF],  g_xlo[BB*SS*FF];
__device__ __nv_bfloat16 g_Wqhi[DKK*FF],   g_Wqlo[DKK*FF];
__device__ __nv_bfloat16 g_Wkhi[DKK*FF],   g_Wklo[DKK*FF];
__device__ __nv_bfloat16 g_Wvhi[DKK*FF],   g_Wvlo[DKK*FF];
__device__ __nv_bfloat16 g_Wohi[FF*DKK],   g_Wolo[FF*DKK];
__device__ __nv_bfloat16 g_qhi[BB*SS*DKK], g_qlo[BB*SS*DKK];
__device__ __nv_bfloat16 g_khi[BB*SS*DKK], g_klo[BB*SS*DKK];
__device__ __nv_bfloat16 g_vhi[BB*SS*DKK], g_vlo[BB*SS*DKK];
__device__ __nv_bfloat16 g_vThi[BB*DKK*SS], g_vTlo[BB*DKK*SS];
__device__ float         g_s[(size_t)BB*SS*SS];
__device__ __nv_bfloat16 g_Ehi[(size_t)BB*SS*SS], g_Elo[(size_t)BB*SS*SS];
__device__ __nv_bfloat16 g_chi[BB*SS*DKK], g_clo[BB*SS*DKK];

// ---------------- PTX helpers (arch-portable: sm_80+ features only) ----------
__device__ __forceinline__ uint32_t smem_to_u32(const void* p) {
    uint32_t a;
    asm("{ .reg .u64 t; cvta.to.shared.u64 t, %1; cvt.u32.u64 %0, t; }" : "=r"(a) : "l"(p));
    return a;
}
__device__ __forceinline__ void cp16(uint32_t dst, const void* src) {
    asm volatile("cp.async.cg.shared.global [%0], [%1], 16;" :: "r"(dst), "l"(src));
}
#define CP_COMMIT() asm volatile("cp.async.commit_group;" ::: "memory")
template <int N> __device__ __forceinline__ void cp_wait() {
    asm volatile("cp.async.wait_group %0;" :: "n"(N) : "memory");
}
__device__ __forceinline__ void ldmx4(uint32_t* r, uint32_t addr) {
    asm volatile("ldmatrix.sync.aligned.m8n8.x4.shared.b16 {%0,%1,%2,%3}, [%4];"
        : "=r"(r[0]), "=r"(r[1]), "=r"(r[2]), "=r"(r[3]) : "r"(addr));
}
__device__ __forceinline__ void mma16816(float* c, const uint32_t* a, const uint32_t* b) {
    asm volatile(
        "mma.sync.aligned.m16n8k16.row.col.f32.bf16.bf16.f32 "
        "{%0,%1,%2,%3}, {%4,%5,%6,%7}, {%8,%9}, {%0,%1,%2,%3};"
        : "+f"(c[0]), "+f"(c[1]), "+f"(c[2]), "+f"(c[3])
        : "r"(a[0]), "r"(a[1]), "r"(a[2]), "r"(a[3]), "r"(b[0]), "r"(b[1]));
}

// smem geometry: 4 planes of 128 rows x 64 bf16 (128B) @ stride 144B
// (144*i mod 128 = 16*i -> all eight 16B banks -> conflict-free ldmatrix)
#define BK     64
#define STRB   144
#define PLANE  (128 * STRB)          // 18432 B
#define BUFSZ  (4 * PLANE)           // 73728 B
#define STAGES 3
#define SMEM_TOTAL (STAGES * BUFSZ)  // 221184 B

// ---------------------------------------------------------------------------
// NT GEMM via mma.sync, bf16 hi/lo split (3 MMA terms):
//   C = alpha * (A . B^T) + bias,   A: M x K, B: N x K (both K-contiguous)
// Output fp32 (Cf) and/or bf16 hi/lo planes (Chi/Clo).
// Pipeline: 3-stage cp.async, one __syncthreads per 64-K chunk.
// ---------------------------------------------------------------------------
__global__ __launch_bounds__(256) void gemm_tc(
    const __nv_bfloat16* __restrict__ Ahi, const __nv_bfloat16* __restrict__ Alo,
    const __nv_bfloat16* __restrict__ Bhi, const __nv_bfloat16* __restrict__ Blo,
    float* __restrict__ Cf, __nv_bfloat16* __restrict__ Chi, __nv_bfloat16* __restrict__ Clo,
    const float* __restrict__ bias,
    int K, int lda, int ldb, int ldc,
    long long sA, long long sB, long long sC, float alpha)
{
    extern __shared__ char smem[];
    uint32_t sbase = smem_to_u32(smem);
    int tid = threadIdx.x;
    int lane = tid & 31;
    int warp = tid >> 5;
    int m0w = (warp >> 1) * 32;     // warp tile 32(m) x 64(n), 4x2 warps
    int n0w = (warp & 1) * 64;

    int bz = blockIdx.z;
    size_t bm = (size_t)blockIdx.y * 128;
    size_t bn = (size_t)blockIdx.x * 128;

    const __nv_bfloat16* A0 = Ahi + (size_t)bz * sA + bm * lda;
    const __nv_bfloat16* A1 = Alo + (size_t)bz * sA + bm * lda;
    const __nv_bfloat16* B0 = Bhi + (size_t)bz * sB + bn * ldb;
    const __nv_bfloat16* B1 = Blo + (size_t)bz * sB + bn * ldb;

    float acc[2][8][4];
#pragma unroll
    for (int i = 0; i < 2; i++)
#pragma unroll
        for (int j = 0; j < 8; j++)
#pragma unroll
            for (int t = 0; t < 4; t++) acc[i][j][t] = 0.0f;

    int nch = K >> 6;   // K/64 chunks

    auto prefetch = [&](int c) {
        int k0 = c << 6;
        uint32_t sb = sbase + (uint32_t)(c % STAGES) * BUFSZ;
#pragma unroll
        for (int it = 0; it < 4; it++) {
            int id = tid + it * 256;          // 0..1023
            int row = id >> 3;                // 0..127
            int seg = id & 7;                 // 0..7 (16B segments of 128B row)
            uint32_t doff = (uint32_t)(row * STRB + seg * 16);
            size_t ea = (size_t)row * lda + k0 + seg * 8;
            size_t eb = (size_t)row * ldb + k0 + seg * 8;
            cp16(sb + 0 * PLANE + doff, A0 + ea);
            cp16(sb + 1 * PLANE + doff, A1 + ea);
            cp16(sb + 2 * PLANE + doff, B0 + eb);
            cp16(sb + 3 * PLANE + doff, B1 + eb);
        }
    };

    // per-lane ldmatrix address pieces
    int aRow = m0w + (lane & 15);
    uint32_t aColB = (uint32_t)((lane >> 4) * 16);
    int bRow = n0w + ((lane >> 4) << 3) + (lane & 7);
    uint32_t bColB = (uint32_t)(((lane >> 3) & 1) * 16);

    prefetch(0); CP_COMMIT();
    if (nch > 1) { prefetch(1); CP_COMMIT(); }

    for (int c = 0; c < nch; c++) {
        cp_wait<1>();          // chunk c arrived (groups complete in order)
        __syncthreads();       // also WAR-guards the buffer prefetch below reuses
        if (c + 2 < nch) { prefetch(c + 2); CP_COMMIT(); }

        uint32_t sb = sbase + (uint32_t)(c % STAGES) * BUFSZ;
#pragma unroll
        for (int ks = 0; ks < 4; ks++) {
            uint32_t kB = (uint32_t)(ks * 32);
            uint32_t a_hi[2][4], a_lo[2][4];
#pragma unroll
            for (int mf = 0; mf < 2; mf++) {
                uint32_t off = (uint32_t)((aRow + mf * 16) * STRB) + kB + aColB;
                ldmx4(a_hi[mf], sb + 0 * PLANE + off);
                ldmx4(a_lo[mf], sb + 1 * PLANE + off);
            }
            uint32_t b_hi[16], b_lo[16];
#pragma unroll
            for (int ng = 0; ng < 4; ng++) {
                uint32_t off = (uint32_t)((bRow + ng * 16) * STRB) + kB + bColB;
                ldmx4(&b_hi[ng * 4], sb + 2 * PLANE + off);
                ldmx4(&b_lo[ng * 4], sb + 3 * PLANE + off);
            }
#pragma unroll
            for (int mf = 0; mf < 2; mf++)
#pragma unroll
                for (int nf = 0; nf < 8; nf++) {
                    mma16816(acc[mf][nf], a_hi[mf], &b_hi[nf * 2]);
                    mma16816(acc[mf][nf], a_hi[mf], &b_lo[nf * 2]);
                    mma16816(acc[mf][nf], a_lo[mf], &b_hi[nf * 2]);
                }
        }
    }

    // epilogue
    int gidr = lane >> 2;
    int tidq = lane & 3;
#pragma unroll
    for (int mf = 0; mf < 2; mf++) {
#pragma unroll
        for (int nf = 0; nf < 8; nf++) {
            size_t r0 = bm + m0w + mf * 16 + gidr;
            size_t r1 = r0 + 8;
            size_t col = bn + n0w + nf * 8 + tidq * 2;
            float b0 = bias ? bias[col] : 0.0f;
            float b1 = bias ? bias[col + 1] : 0.0f;
            float c00 = acc[mf][nf][0] * alpha + b0;
            float c01 = acc[mf][nf][1] * alpha + b1;
            float c10 = acc[mf][nf][2] * alpha + b0;
            float c11 = acc[mf][nf][3] * alpha + b1;
            if (Cf) {
                float* base = Cf + (size_t)bz * sC;
                *(float2*)(base + r0 * ldc + col) = make_float2(c00, c01);
                *(float2*)(base + r1 * ldc + col) = make_float2(c10, c11);
            }
            if (Chi) {
                __nv_bfloat16* bh = Chi + (size_t)bz * sC;
                __nv_bfloat16* bl = Clo + (size_t)bz * sC;
                __nv_bfloat162 h0 = __floats2bfloat162_rn(c00, c01);
                __nv_bfloat162 h1 = __floats2bfloat162_rn(c10, c11);
                __nv_bfloat162 l0 = __floats2bfloat162_rn(
                    c00 - __bfloat162float(__low2bfloat16(h0)),
                    c01 - __bfloat162float(__high2bfloat16(h0)));
                __nv_bfloat162 l1 = __floats2bfloat162_rn(
                    c10 - __bfloat162float(__low2bfloat16(h1)),
                    c11 - __bfloat162float(__high2bfloat16(h1)));
                *(__nv_bfloat162*)(bh + r0 * ldc + col) = h0;
                *(__nv_bfloat162*)(bh + r1 * ldc + col) = h1;
                *(__nv_bfloat162*)(bl + r0 * ldc + col) = l0;
                *(__nv_bfloat162*)(bl + r1 * ldc + col) = l1;
            }
        }
    }
}

// ---------------------------------------------------------------------------
// fp32 -> bf16 hi/lo split conversion
// ---------------------------------------------------------------------------
__global__ __launch_bounds__(256) void conv_split(
    const float* __restrict__ in, __nv_bfloat16* __restrict__ hi,
    __nv_bfloat16* __restrict__ lo, long long n4)
{
    long long i = (long long)blockIdx.x * blockDim.x + threadIdx.x;
    if (i >= n4) return;
    float4 v = ((const float4*)in)[i];
    __nv_bfloat162 h0 = __floats2bfloat162_rn(v.x, v.y);
    __nv_bfloat162 h1 = __floats2bfloat162_rn(v.z, v.w);
    float r0 = v.x - __bfloat162float(__low2bfloat16(h0));
    float r1 = v.y - __bfloat162float(__high2bfloat16(h0));
    float r2 = v.z - __bfloat162float(__low2bfloat16(h1));
    float r3 = v.w - __bfloat162float(__high2bfloat16(h1));
    ((__nv_bfloat162*)hi)[2 * i] = h0;
    ((__nv_bfloat162*)hi)[2 * i + 1] = h1;
    ((__nv_bfloat162*)lo)[2 * i] = __floats2bfloat162_rn(r0, r1);
    ((__nv_bfloat162*)lo)[2 * i + 1] = __floats2bfloat162_rn(r2, r3);
}

// ---------------------------------------------------------------------------
// Column softmax (over query axis) with folded 1/sum; writes E hi/lo bf16.
// ---------------------------------------------------------------------------
__global__ __launch_bounds__(256) void colsoftmax(
    const float* __restrict__ S, __nv_bfloat16* __restrict__ Ehi,
    __nv_bfloat16* __restrict__ Elo)
{
    __shared__ float red[4][64];
    int b = blockIdx.y;
    int cx = threadIdx.x & 63;
    int cy = threadIdx.x >> 6;
    size_t k = (size_t)blockIdx.x * 64 + cx;
    const float* p = S + (size_t)b * SS * SS + k;
    const int CH = SS / 4;
    int q0 = cy * CH;

    float m = -1e30f;
    for (int q = q0; q < q0 + CH; q++)
        m = fmaxf(m, p[(size_t)q * SS]);
    red[cy][cx] = m;
    __syncthreads();
    m = fmaxf(fmaxf(red[0][cx], red[1][cx]), fmaxf(red[2][cx], red[3][cx]));
    __syncthreads();

    float sum = 0.0f;
    for (int q = q0; q < q0 + CH; q++)
        sum += __expf(p[(size_t)q * SS] - m);
    red[cy][cx] = sum;
    __syncthreads();
    float rcp = 1.0f / (red[0][cx] + red[1][cx] + red[2][cx] + red[3][cx]);

    __nv_bfloat16* eh = Ehi + (size_t)b * SS * SS + k;
    __nv_bfloat16* el = Elo + (size_t)b * SS * SS + k;
    for (int q = q0; q < q0 + CH; q++) {
        float e = __expf(p[(size_t)q * SS] - m) * rcp;
        __nv_bfloat16 h = __float2bfloat16(e);
        eh[(size_t)q * SS] = h;
        el[(size_t)q * SS] = __float2bfloat16(e - __bfloat162float(h));
    }
}

// ---------------------------------------------------------------------------
// bf16 transpose (both planes), batched.
// ---------------------------------------------------------------------------
__global__ __launch_bounds__(256) void transpose2(
    const __nv_bfloat16* __restrict__ ihi, const __nv_bfloat16* __restrict__ ilo,
    __nv_bfloat16* __restrict__ ohi, __nv_bfloat16* __restrict__ olo,
    int rows, int cols)
{
    __shared__ __nv_bfloat16 t[32][33];
    int z = blockIdx.z;
    size_t ioff = (size_t)z * rows * cols;
    int c0 = blockIdx.x * 32, r0 = blockIdx.y * 32;
    int tx = threadIdx.x, ty = threadIdx.y;

    const __nv_bfloat16* src = ihi + ioff;
    __nv_bfloat16* dst = ohi + ioff;
#pragma unroll
    for (int j = 0; j < 32; j += 8)
        t[ty + j][tx] = src[(size_t)(r0 + ty + j) * cols + c0 + tx];
    __syncthreads();
#pragma unroll
    for (int j = 0; j < 32; j += 8)
        dst[(size_t)(c0 + ty + j) * rows + r0 + tx] = t[tx][ty + j];
    __syncthreads();

    src = ilo + ioff;
    dst = olo + ioff;
#pragma unroll
    for (int j = 0; j < 32; j += 8)
        t[ty + j][tx] = src[(size_t)(r0 + ty + j) * cols + c0 + tx];
    __syncthreads();
#pragma unroll
    for (int j = 0; j < 32; j += 8)
        dst[(size_t)(c0 + ty + j) * rows + r0 + tx] = t[tx][ty + j];
}

// ---------------------------------------------------------------------------
extern "C" void kernel_launch(void* const* d_in, const int* in_sizes, int n_in,
                              void* d_out, int out_size)
{
    const float* x  = (const float*)d_in[0];
    const float* Wq = (const float*)d_in[1];
    const float* bq = (const float*)d_in[2];
    const float* Wk = (const float*)d_in[3];
    const float* bk = (const float*)d_in[4];
    const float* Wv = (const float*)d_in[5];
    const float* bv = (const float*)d_in[6];
    const float* Wo = (const float*)d_in[7];
    const float* bo = (const float*)d_in[8];

    __nv_bfloat16 *xhi, *xlo, *Wqhi, *Wqlo, *Wkhi, *Wklo, *Wvhi, *Wvlo, *Wohi, *Wolo;
    __nv_bfloat16 *qhi, *qlo, *khi, *klo, *vhi, *vlo, *vThi, *vTlo, *Ehi, *Elo, *chi, *clo;
    float* s;
    cudaGetSymbolAddress((void**)&xhi, g_xhi);   cudaGetSymbolAddress((void**)&xlo, g_xlo);
    cudaGetSymbolAddress((void**)&Wqhi, g_Wqhi); cudaGetSymbolAddress((void**)&Wqlo, g_Wqlo);
    cudaGetSymbolAddress((void**)&Wkhi, g_Wkhi); cudaGetSymbolAddress((void**)&Wklo, g_Wklo);
    cudaGetSymbolAddress((void**)&Wvhi, g_Wvhi); cudaGetSymbolAddress((void**)&Wvlo, g_Wvlo);
    cudaGetSymbolAddress((void**)&Wohi, g_Wohi); cudaGetSymbolAddress((void**)&Wolo, g_Wolo);
    cudaGetSymbolAddress((void**)&qhi, g_qhi);   cudaGetSymbolAddress((void**)&qlo, g_qlo);
    cudaGetSymbolAddress((void**)&khi, g_khi);   cudaGetSymbolAddress((void**)&klo, g_klo);
    cudaGetSymbolAddress((void**)&vhi, g_vhi);   cudaGetSymbolAddress((void**)&vlo, g_vlo);
    cudaGetSymbolAddress((void**)&vThi, g_vThi); cudaGetSymbolAddress((void**)&vTlo, g_vTlo);
    cudaGetSymbolAddress((void**)&Ehi, g_Ehi);   cudaGetSymbolAddress((void**)&Elo, g_Elo);
    cudaGetSymbolAddress((void**)&chi, g_chi);   cudaGetSymbolAddress((void**)&clo, g_clo);
    cudaGetSymbolAddress((void**)&s, g_s);

    cudaFuncSetAttribute(gemm_tc, cudaFuncAttributeMaxDynamicSharedMemorySize, SMEM_TOTAL);

    const int M = BB * SS;  // 8192
    dim3 blk(256);

    // 0) conversions
    conv_split<<<(M * FF / 4 + 255) / 256, 256>>>(x, xhi, xlo, (long long)M * FF / 4);
    conv_split<<<(DKK * FF / 4 + 255) / 256, 256>>>(Wq, Wqhi, Wqlo, (long long)DKK * FF / 4);
    conv_split<<<(DKK * FF / 4 + 255) / 256, 256>>>(Wk, Wkhi, Wklo, (long long)DKK * FF / 4);
    conv_split<<<(DKK * FF / 4 + 255) / 256, 256>>>(Wv, Wvhi, Wvlo, (long long)DKK * FF / 4);
    conv_split<<<(FF * DKK / 4 + 255) / 256, 256>>>(Wo, Wohi, Wolo, (long long)FF * DKK / 4);

    // 1) QKV projections -> bf16 hi/lo (+bias)
    dim3 g1(DKK / 128, M / 128, 1);
    gemm_tc<<<g1, blk, SMEM_TOTAL>>>(xhi, xlo, Wqhi, Wqlo, nullptr, qhi, qlo, bq,
                                     FF, FF, FF, DKK, 0, 0, 0, 1.0f);
    gemm_tc<<<g1, blk, SMEM_TOTAL>>>(xhi, xlo, Wkhi, Wklo, nullptr, khi, klo, bk,
                                     FF, FF, FF, DKK, 0, 0, 0, 1.0f);
    gemm_tc<<<g1, blk, SMEM_TOTAL>>>(xhi, xlo, Wvhi, Wvlo, nullptr, vhi, vlo, bv,
                                     FF, FF, FF, DKK, 0, 0, 0, 1.0f);

    // 2) scores = (q k^T)/32 -> fp32 S (batched)
    dim3 g2(SS / 128, SS / 128, BB);
    gemm_tc<<<g2, blk, SMEM_TOTAL>>>(qhi, qlo, khi, klo, s, nullptr, nullptr, nullptr,
                                     DKK, DKK, DKK, SS,
                                     (long long)SS * DKK, (long long)SS * DKK,
                                     (long long)SS * SS, 1.0f / 32.0f);

    // 3) column softmax -> E hi/lo (1/sum folded)
    dim3 g3(SS / 64, BB);
    colsoftmax<<<g3, blk>>>(s, Ehi, Elo);

    // 4) transpose v -> vT (per batch)
    dim3 g4(DKK / 32, SS / 32, BB);
    transpose2<<<g4, dim3(32, 8)>>>(vhi, vlo, vThi, vTlo, SS, DKK);

    // 5) ctx = E @ V  (NT with B = vT) -> bf16 hi/lo
    dim3 g5(DKK / 128, SS / 128, BB);
    gemm_tc<<<g5, blk, SMEM_TOTAL>>>(Ehi, Elo, vThi, vTlo, nullptr, chi, clo, nullptr,
                                     SS, SS, SS, DKK,
                                     (long long)SS * SS, (long long)DKK * SS,
                                     (long long)SS * DKK, 1.0f);

    // 6) out = ctx @ Wo^T + bo -> fp32
    dim3 g6(FF / 128, M / 128, 1);
    gemm_tc<<<g6, blk, SMEM_TOTAL>>>(chi, clo, Wohi, Wolo, (float*)d_out, nullptr, nullptr, bo,
                                     DKK, DKK, DKK, FF, 0, 0, 0, 1.0f);
}